// round 8
// baseline (speedup 1.0000x reference)
#include <cuda_runtime.h>
#include <cstdint>

// ---------------- problem constants ----------------
#define NN    50000      // nodes
#define EE    800000     // edges
#define GG    256        // graphs
#define LL    3          // layers
#define DD    300        // hidden dim
#define D2    600        // 2*D
#define NF    128        // node feat
#define EFD   16         // edge feat
#define OUTD  128        // output dim
#define NP1   (NN + 1)
#define DP    (DD / 2)   // 150 column pairs

// packed fp32x2 helpers (sm_100+; ptxas never auto-fuses these)
#define FMA_F32X2(d, a, b, c) \
    asm("fma.rn.f32x2 %0, %1, %2, %3;" : "=l"(d) : "l"(a), "l"(b), "l"(c))
#define ADD_F32X2(d, a, b) \
    asm("add.rn.f32x2 %0, %1, %2;" : "=l"(d) : "l"(a), "l"(b))
#define PACK_DUP_F32X2(d, f) \
    asm("mov.b64 %0, {%1, %1};" : "=l"(d) : "f"(f))
#define PACK_F32X2(d, lo, hi) \
    asm("mov.b64 %0, {%1, %2};" : "=l"(d) : "f"(lo), "f"(hi))
#define UNPACK_F32X2(lo, hi, p) \
    asm("mov.b64 {%0, %1}, %2;" : "=f"(lo), "=f"(hi) : "l"(p))

typedef unsigned long long u64;

// ---------------- scratch (static device memory; no allocs allowed) ---------
__device__ float  g_hn[(size_t)NN * DD];       // 60 MB
__device__ float  g_A [(size_t)NN * DD];       // 60 MB  (edge-agg out / Y2)
__device__ float  g_Y1[(size_t)NN * D2];       // 120 MB
__device__ int    g_rowptr[NP1];               // CSR row ptr (also the histogram)
__device__ int    g_cursor[NN];
__device__ int    g_eidx[EE];
__device__ int    g_blockSums[64];
__device__ double g_sums1[D2];                 // BN1 stats (GEMM1 epilogue)
__device__ double g_sqs1 [D2];
__device__ double g_sums2[DD];                 // BN2 stats (GEMM2 epilogue)
__device__ double g_sqs2 [DD];
__device__ float  g_scale[D2];
__device__ float  g_shift[D2];
__device__ float  g_hg[GG * DD];
__device__ float  g_cnt[GG];

// ---------------- CSR build ----------------
__global__ void count_kernel(const int* __restrict__ dst, int* __restrict__ hist) {
    int e = blockIdx.x * blockDim.x + threadIdx.x;
    if (e < EE) atomicAdd(&hist[dst[e] + 1], 1);
}

// inclusive scan, 1024-wide blocks (Hillis-Steele)
__global__ void scan1_kernel(int* data, int* blockSums, int n) {
    __shared__ int sh[1024];
    int tid = threadIdx.x;
    int i = blockIdx.x * 1024 + tid;
    int v = (i < n) ? data[i] : 0;
    sh[tid] = v; __syncthreads();
    for (int off = 1; off < 1024; off <<= 1) {
        int t = (tid >= off) ? sh[tid - off] : 0;
        __syncthreads();
        sh[tid] += t;
        __syncthreads();
    }
    if (i < n) data[i] = sh[tid];
    if (tid == 1023) blockSums[blockIdx.x] = sh[1023];
}
__global__ void scan2_kernel(int* blockSums, int nb) {
    __shared__ int sh[64];
    int tid = threadIdx.x;
    int v = (tid < nb) ? blockSums[tid] : 0;
    sh[tid] = v; __syncthreads();
    for (int off = 1; off < 64; off <<= 1) {
        int t = (tid >= off) ? sh[tid - off] : 0;
        __syncthreads();
        sh[tid] += t;
        __syncthreads();
    }
    if (tid < nb) blockSums[tid] = (tid == 0) ? 0 : sh[tid - 1]; // exclusive
}
__global__ void scan3_kernel(int* data, const int* blockSums, int n) {
    int i = blockIdx.x * 1024 + threadIdx.x;
    if (i < n && blockIdx.x > 0) data[i] += blockSums[blockIdx.x];
}
__global__ void cursor_copy_kernel(const int* __restrict__ rowptr, int* __restrict__ cur) {
    int v = blockIdx.x * blockDim.x + threadIdx.x;
    if (v < NN) cur[v] = rowptr[v];
}
__global__ void fill_kernel(const int* __restrict__ dst, int* __restrict__ cur,
                            int* __restrict__ eidx) {
    int e = blockIdx.x * blockDim.x + threadIdx.x;
    if (e < EE) {
        int pos = atomicAdd(&cur[dst[e]], 1);
        eidx[pos] = e;
    }
}

// ---------------- fused edge encoder + gather + relu + pull-aggregate --------
// outA[v] = hn[v] + sum_{e: dst(e)=v} relu(hn[src(e)] + edge_feat[e] @ eW + eb)
// One warp per node; each lane owns 5 column PAIRS (f32x2 datapath throughout).
// Software-pipelined edge loop (prefetch next eid/src/feat).
__global__ void edge_agg_kernel(const float* __restrict__ hn,
                                const float* __restrict__ edge_feat,
                                const int*   __restrict__ src,
                                const int*   __restrict__ eidx,
                                const int*   __restrict__ rowptr,
                                const float* __restrict__ eW,
                                const float* __restrict__ eb,
                                float* __restrict__ outA) {
    __shared__ float sW[EFD * DD];   // 19200 B  (row k: 300 floats, 8B-aligned pairs)
    __shared__ float sB[DD];
    for (int i = threadIdx.x; i < EFD * DD; i += blockDim.x) sW[i] = eW[i];
    for (int i = threadIdx.x; i < DD; i += blockDim.x) sB[i] = eb[i];
    __syncthreads();

    const int lane  = threadIdx.x & 31;
    const int warp  = threadIdx.x >> 5;
    const int wpb   = blockDim.x >> 5;
    const int nWarp = gridDim.x * wpb;

    // bias pairs: invariant across nodes and edges — hoist
    u64 bb2[5];
#pragma unroll
    for (int t = 0; t < 5; t++) {
        int j2 = lane + 32 * t;
        bb2[t] = (j2 < DP) ? *reinterpret_cast<const u64*>(&sB[2 * j2]) : 0ull;
    }

    for (int v = blockIdx.x * wpb + warp; v < NN; v += nWarp) {
        u64 acc2[5];
        const u64* hv2 = reinterpret_cast<const u64*>(hn + (size_t)v * DD);
#pragma unroll
        for (int t = 0; t < 5; t++) {
            int j2 = lane + 32 * t;
            acc2[t] = (j2 < DP) ? hv2[j2] : 0ull;
        }
        const int e0 = rowptr[v], e1 = rowptr[v + 1];
        if (e0 < e1) {
            // prefetch edge e0
            int eid = eidx[e0];
            int s   = src[eid];
            const float4* efp = reinterpret_cast<const float4*>(edge_feat) + (size_t)eid * 4;
            float4 f0 = __ldg(efp + 0), f1 = __ldg(efp + 1);
            float4 f2 = __ldg(efp + 2), f3 = __ldg(efp + 3);
            for (int e = e0; e < e1; e++) {
                const int    s_cur = s;
                const float4 c0 = f0, c1 = f1, c2 = f2, c3 = f3;
                // issue next edge's index/feature loads before consuming current
                if (e + 1 < e1) {
                    eid = eidx[e + 1];
                    s   = src[eid];
                    const float4* nfp =
                        reinterpret_cast<const float4*>(edge_feat) + (size_t)eid * 4;
                    f0 = __ldg(nfp + 0); f1 = __ldg(nfp + 1);
                    f2 = __ldg(nfp + 2); f3 = __ldg(nfp + 3);
                }
                // duplicate-pack the 16 edge features (warp-uniform scalars)
                float ef[16] = { c0.x, c0.y, c0.z, c0.w, c1.x, c1.y, c1.z, c1.w,
                                 c2.x, c2.y, c2.z, c2.w, c3.x, c3.y, c3.z, c3.w };
                u64 ef2[16];
#pragma unroll
                for (int k = 0; k < EFD; k++) PACK_DUP_F32X2(ef2[k], ef[k]);

                const u64* hs2 = reinterpret_cast<const u64*>(hn + (size_t)s_cur * DD);
#pragma unroll
                for (int t = 0; t < 5; t++) {
                    int j2 = lane + 32 * t;
                    if (j2 < DP) {
                        u64 he2 = bb2[t];
#pragma unroll
                        for (int k = 0; k < EFD; k++) {
                            u64 w2 = *reinterpret_cast<const u64*>(&sW[k * DD + 2 * j2]);
                            FMA_F32X2(he2, ef2[k], w2, he2);
                        }
                        u64 hsv = hs2[j2];
                        ADD_F32X2(he2, he2, hsv);       // msg = he + hn[src]
                        float lo, hi;
                        UNPACK_F32X2(lo, hi, he2);
                        lo = fmaxf(lo, 0.f);
                        hi = fmaxf(hi, 0.f);
                        u64 m2;
                        PACK_F32X2(m2, lo, hi);
                        ADD_F32X2(acc2[t], acc2[t], m2);
                    }
                }
            }
        }
        u64* ov2 = reinterpret_cast<u64*>(outA + (size_t)v * DD);
#pragma unroll
        for (int t = 0; t < 5; t++) {
            int j2 = lane + 32 * t;
            if (j2 < DP) ov2[j2] = acc2[t];
        }
    }
}

// ------ tiled SGEMM (packed f32x2 FMA, double-buffered), templated tile -----
// C = f(A)[M,K] @ B[K,N] + bias,  f(a_{rc}) = max(a*aScale[c]+aShift[c], 0) if aScale
// Optional fused column statistics: if oSums != nullptr, accumulates
// sum_r C[r][c] and sum_r C[r][c]^2 in double into oSums/oSqs (for BatchNorm).
#define GBK 16
template<int BM, int BN>
__global__ __launch_bounds__(256, 1)
void gemm_bias_t(const float* __restrict__ A, const float* __restrict__ B,
                 const float* __restrict__ bias, float* __restrict__ C,
                 int M_, int N_, int K_,
                 const float* __restrict__ aScale, const float* __restrict__ aShift,
                 double* __restrict__ oSums, double* __restrict__ oSqs) {
    constexpr int CG  = BN / 8;           // column groups of 8
    constexpr int RG  = BM / 8;           // row groups of 8
    static_assert(CG * RG == 256, "micro-tile grid must equal 256 threads");
    constexpr int APD = BM + 4;           // A-tile row pad (bank stagger)
    constexpr int ASLOT = BM * 4;         // float4 slots in A tile (BM x 16 / 4)
    constexpr int BSLOT = 4 * BN;         // float4 slots in B tile (16 x BN / 4)
    constexpr int APT = ASLOT / 256;      // per-thread A slots
    constexpr int BPT = BSLOT / 256;      // per-thread B slots
    static_assert(APT * 256 == ASLOT && BPT * 256 == BSLOT, "slot coverage");
    constexpr int BQ = BN / 4;            // float4s per B row

    __shared__ float As[2][GBK][APD];
    __shared__ float Bs[2][GBK][BN];
    __shared__ double sSum[BN];
    __shared__ double sSqs[BN];
    const int tid = threadIdx.x;
    const int ty = tid / CG, tx = tid % CG;
    const int rowBase = blockIdx.y * BM;
    const int colBase = blockIdx.x * BN;

    unsigned long long acc2[8][4];        // 8 rows x 4 packed column-pairs
#pragma unroll
    for (int i = 0; i < 8; i++)
#pragma unroll
        for (int j = 0; j < 4; j++) acc2[i][j] = 0ull;

    float4 pa[APT], pb[BPT];
    int    pac[APT];
    bool   pav[APT];

    auto fetchA = [&](int kb, int slot, int w) {
        int r  = slot >> 2;
        int c4 = (slot & 3) * 4;
        int gr = rowBase + r;
        int gc = kb + c4;
        float4 v = make_float4(0.f, 0.f, 0.f, 0.f);
        if (gr < M_) {
            if (gc + 3 < K_) {
                v = *reinterpret_cast<const float4*>(A + (size_t)gr * K_ + gc);
            } else {
                if (gc + 0 < K_) v.x = A[(size_t)gr * K_ + gc + 0];
                if (gc + 1 < K_) v.y = A[(size_t)gr * K_ + gc + 1];
                if (gc + 2 < K_) v.z = A[(size_t)gr * K_ + gc + 2];
                if (gc + 3 < K_) v.w = A[(size_t)gr * K_ + gc + 3];
            }
        }
        pa[w] = v; pav[w] = (gr < M_); pac[w] = gc;
    };
    auto storeA = [&](int buf, int slot, int w) {
        int r  = slot >> 2;
        int c4 = (slot & 3) * 4;
        float4 v = pa[w];
        int gc = pac[w];
        if (aScale && pav[w]) {   // fused BN + ReLU on the A operand (per K-channel)
            if (gc + 0 < K_) v.x = fmaxf(fmaf(v.x, aScale[gc + 0], aShift[gc + 0]), 0.f);
            if (gc + 1 < K_) v.y = fmaxf(fmaf(v.y, aScale[gc + 1], aShift[gc + 1]), 0.f);
            if (gc + 2 < K_) v.z = fmaxf(fmaf(v.z, aScale[gc + 2], aShift[gc + 2]), 0.f);
            if (gc + 3 < K_) v.w = fmaxf(fmaf(v.w, aScale[gc + 3], aShift[gc + 3]), 0.f);
        }
        As[buf][c4 + 0][r] = v.x;
        As[buf][c4 + 1][r] = v.y;
        As[buf][c4 + 2][r] = v.z;
        As[buf][c4 + 3][r] = v.w;
    };
    auto fetchB = [&](int kb, int slot, int w) {
        int r  = slot / BQ;
        int c4 = (slot % BQ) * 4;
        int gr = kb + r;
        int gc = colBase + c4;
        float4 v = make_float4(0.f, 0.f, 0.f, 0.f);
        if (gr < K_) {
            if (gc + 3 < N_) {
                v = *reinterpret_cast<const float4*>(B + (size_t)gr * N_ + gc);
            } else {
                if (gc + 0 < N_) v.x = B[(size_t)gr * N_ + gc + 0];
                if (gc + 1 < N_) v.y = B[(size_t)gr * N_ + gc + 1];
                if (gc + 2 < N_) v.z = B[(size_t)gr * N_ + gc + 2];
                if (gc + 3 < N_) v.w = B[(size_t)gr * N_ + gc + 3];
            }
        }
        pb[w] = v;
    };
    auto storeB = [&](int buf, int slot, int w) {
        int r  = slot / BQ;
        int c4 = (slot % BQ) * 4;
        *reinterpret_cast<float4*>(&Bs[buf][r][c4]) = pb[w];
    };

    // zero the stats staging while the first tile loads
    if (oSums) {
        for (int c = tid; c < BN; c += 256) { sSum[c] = 0.0; sSqs[c] = 0.0; }
    }

    // ---- prologue: tile 0 into buffer 0 ----
#pragma unroll
    for (int i = 0; i < APT; i++) { fetchA(0, tid + i * 256, i); }
#pragma unroll
    for (int i = 0; i < APT; i++) { storeA(0, tid + i * 256, i); }
#pragma unroll
    for (int i = 0; i < BPT; i++) { fetchB(0, tid + i * 256, i); }
#pragma unroll
    for (int i = 0; i < BPT; i++) { storeB(0, tid + i * 256, i); }
    __syncthreads();

    int buf = 0;
    for (int kb = 0; kb < K_; kb += GBK) {
        const int nxt = kb + GBK;
        const bool more = (nxt < K_);
        if (more) {       // prefetch next tile into registers
#pragma unroll
            for (int i = 0; i < APT; i++) fetchA(nxt, tid + i * 256, i);
#pragma unroll
            for (int i = 0; i < BPT; i++) fetchB(nxt, tid + i * 256, i);
        }
        // compute on current buffer
#pragma unroll
        for (int k = 0; k < GBK; k++) {
            float4 a0 = *reinterpret_cast<const float4*>(&As[buf][k][ty * 8]);
            float4 a1 = *reinterpret_cast<const float4*>(&As[buf][k][ty * 8 + 4]);
            float ra[8] = { a0.x, a0.y, a0.z, a0.w, a1.x, a1.y, a1.z, a1.w };
            unsigned long long ra2[8];
#pragma unroll
            for (int i = 0; i < 8; i++) PACK_DUP_F32X2(ra2[i], ra[i]);
            ulonglong2 bq0 = *reinterpret_cast<const ulonglong2*>(&Bs[buf][k][tx * 8]);
            ulonglong2 bq1 = *reinterpret_cast<const ulonglong2*>(&Bs[buf][k][tx * 8 + 4]);
            unsigned long long rb2[4] = { bq0.x, bq0.y, bq1.x, bq1.y };
#pragma unroll
            for (int i = 0; i < 8; i++)
#pragma unroll
                for (int j = 0; j < 4; j++)
                    FMA_F32X2(acc2[i][j], ra2[i], rb2[j], acc2[i][j]);
        }
        if (more) {       // commit prefetched tile to the other buffer
            int nb = buf ^ 1;
#pragma unroll
            for (int i = 0; i < APT; i++) storeA(nb, tid + i * 256, i);
#pragma unroll
            for (int i = 0; i < BPT; i++) storeB(nb, tid + i * 256, i);
            __syncthreads();
            buf = nb;
        }
    }

    // ---- epilogue: bias add, store C, optionally accumulate column stats ----
    double locS[8], locQ[8];
#pragma unroll
    for (int j = 0; j < 8; j++) { locS[j] = 0.0; locQ[j] = 0.0; }

#pragma unroll
    for (int i = 0; i < 8; i++) {
        int gr = rowBase + ty * 8 + i;
        if (gr >= M_) continue;
#pragma unroll
        for (int j = 0; j < 4; j++) {
            int gc = colBase + tx * 8 + 2 * j;
            float lo, hi;
            UNPACK_F32X2(lo, hi, acc2[i][j]);
            if (gc < N_) {
                float v = lo + bias[gc];
                C[(size_t)gr * N_ + gc] = v;
                locS[2 * j]     += (double)v;
                locQ[2 * j]     += (double)v * (double)v;
            }
            if (gc + 1 < N_) {
                float v = hi + bias[gc + 1];
                C[(size_t)gr * N_ + gc + 1] = v;
                locS[2 * j + 1] += (double)v;
                locQ[2 * j + 1] += (double)v * (double)v;
            }
        }
    }
    if (oSums) {
        // smem column reduction (RG contributions per column), then 1 global
        // double atomicAdd per column per block.
#pragma unroll
        for (int j = 0; j < 8; j++) {
            int lc = tx * 8 + j;
            atomicAdd(&sSum[lc], locS[j]);
            atomicAdd(&sSqs[lc], locQ[j]);
        }
        __syncthreads();
        for (int c = tid; c < BN; c += 256) {
            int gc = colBase + c;
            if (gc < N_) {
                atomicAdd(&oSums[gc], sSum[c]);
                atomicAdd(&oSqs[gc],  sSqs[c]);
            }
        }
    }
}

// ---------------- batchnorm coefficient + apply ----------------
__global__ void bn_coeff_kernel(const double* __restrict__ sums, const double* __restrict__ sqs,
                                const float* __restrict__ g, const float* __restrict__ beta,
                                float* __restrict__ scale, float* __restrict__ shift, int C) {
    int c = blockIdx.x * blockDim.x + threadIdx.x;
    if (c >= C) return;
    const double invN = 1.0 / (double)NN;
    double mean = sums[c] * invN;
    double var  = sqs[c] * invN - mean * mean;
    float sc = g[c] * rsqrtf((float)var + 1e-5f);
    scale[c] = sc;
    shift[c] = beta[c] - (float)mean * sc;
}
__global__ void bn_apply_kernel(const float* __restrict__ X, float* __restrict__ Y,
                                const float* __restrict__ scale, const float* __restrict__ shift,
                                int C, int total, int relu) {
    int i = blockIdx.x * blockDim.x + threadIdx.x;
    if (i >= total) return;
    int c = i % C;
    float v = fmaf(X[i], scale[c], shift[c]);
    if (relu) v = fmaxf(v, 0.f);
    Y[i] = v;
}
// final layer: BN2 apply (no relu) fused with avg-pool accumulation (atomics)
__global__ void bn_apply_pool_kernel(const float* __restrict__ X,
                                     const float* __restrict__ scale,
                                     const float* __restrict__ shift,
                                     const int* __restrict__ gid,
                                     float* __restrict__ hg) {
    int i = blockIdx.x * blockDim.x + threadIdx.x;
    if (i >= NN * DD) return;
    int v = i / DD, c = i - v * DD;
    float y = fmaf(X[i], scale[c], shift[c]);
    atomicAdd(&hg[gid[v] * DD + c], y);
}

// ---------------- graph pooling + head ----------------
__global__ void pool_cnt_kernel(const int* __restrict__ gid, float* __restrict__ cnt) {
    int v = blockIdx.x * blockDim.x + threadIdx.x;
    if (v < NN) atomicAdd(&cnt[gid[v]], 1.f);
}
__global__ void head_kernel(const float* __restrict__ hg, const float* __restrict__ cnt,
                            const float* __restrict__ pW, const float* __restrict__ pb,
                            float* __restrict__ out) {
    __shared__ float avg[DD];
    int g = blockIdx.x;
    float c = fmaxf(cnt[g], 1.f);
    for (int d = threadIdx.x; d < DD; d += blockDim.x)
        avg[d] = hg[g * DD + d] / c;
    __syncthreads();
    int o = threadIdx.x;  // 128 threads
    float s = pb[o];
#pragma unroll 4
    for (int d = 0; d < DD; d++)
        s = fmaf(avg[d], pW[d * OUTD + o], s);
    out[g * OUTD + o] = s;
}

// ---------------- orchestration ----------------
extern "C" void kernel_launch(void* const* d_in, const int* in_sizes, int n_in,
                              void* d_out, int out_size) {
    // inputs (robust to whether scalar num_graphs is materialized as an input)
    const int off = n_in - 14;  // 14 trailing parameter tensors
    const float* node_feat = (const float*)d_in[0];
    const float* edge_feat = (const float*)d_in[1];
    const int*   src       = (const int*)  d_in[2];
    const int*   dst       = (const int*)  d_in[3];
    const int*   graph_ids = (const int*)  d_in[4];
    const float* node_W  = (const float*)d_in[off + 0];
    const float* node_b  = (const float*)d_in[off + 1];
    const float* edge_W  = (const float*)d_in[off + 2];
    const float* edge_b  = (const float*)d_in[off + 3];
    const float* W1      = (const float*)d_in[off + 4];
    const float* b1      = (const float*)d_in[off + 5];
    const float* g1      = (const float*)d_in[off + 6];
    const float* beta1   = (const float*)d_in[off + 7];
    const float* W2      = (const float*)d_in[off + 8];
    const float* b2      = (const float*)d_in[off + 9];
    const float* g2      = (const float*)d_in[off + 10];
    const float* beta2   = (const float*)d_in[off + 11];
    const float* pred_W  = (const float*)d_in[off + 12];
    const float* pred_b  = (const float*)d_in[off + 13];
    float* out = (float*)d_out;

    // resolve device-symbol addresses (pure lookup; no allocation, capture-safe)
    float *hn_p, *A_p, *Y1_p, *hg_p, *cnt_p, *scale_p, *shift_p;
    int *rowptr_p, *cursor_p, *eidx_p, *bsum_p;
    double *sums1_p, *sqs1_p, *sums2_p, *sqs2_p;
    cudaGetSymbolAddress((void**)&hn_p, g_hn);
    cudaGetSymbolAddress((void**)&A_p, g_A);
    cudaGetSymbolAddress((void**)&Y1_p, g_Y1);
    cudaGetSymbolAddress((void**)&hg_p, g_hg);
    cudaGetSymbolAddress((void**)&cnt_p, g_cnt);
    cudaGetSymbolAddress((void**)&scale_p, g_scale);
    cudaGetSymbolAddress((void**)&shift_p, g_shift);
    cudaGetSymbolAddress((void**)&rowptr_p, g_rowptr);
    cudaGetSymbolAddress((void**)&cursor_p, g_cursor);
    cudaGetSymbolAddress((void**)&eidx_p, g_eidx);
    cudaGetSymbolAddress((void**)&bsum_p, g_blockSums);
    cudaGetSymbolAddress((void**)&sums1_p, g_sums1);
    cudaGetSymbolAddress((void**)&sqs1_p, g_sqs1);
    cudaGetSymbolAddress((void**)&sums2_p, g_sums2);
    cudaGetSymbolAddress((void**)&sqs2_p, g_sqs2);

    // ---- CSR by dst ----
    cudaMemsetAsync(rowptr_p, 0, NP1 * sizeof(int));
    count_kernel<<<(EE + 255) / 256, 256>>>(dst, rowptr_p);
    const int nScanBlk = (NP1 + 1023) / 1024;  // 49
    scan1_kernel<<<nScanBlk, 1024>>>(rowptr_p, bsum_p, NP1);
    scan2_kernel<<<1, 64>>>(bsum_p, nScanBlk);
    scan3_kernel<<<nScanBlk, 1024>>>(rowptr_p, bsum_p, NP1);
    cursor_copy_kernel<<<(NN + 255) / 256, 256>>>(rowptr_p, cursor_p);
    fill_kernel<<<(EE + 255) / 256, 256>>>(dst, cursor_p, eidx_p);

    // grid helpers
    const dim3 gridN300_256x64((DD + 63) / 64, (NN + 255) / 256);    // 5 x 196
    const dim3 gridN600_128x128((D2 + 127) / 128, (NN + 127) / 128); // 5 x 391

    // ---- node encoder: hn = node_feat @ node_W + node_b  (N=300 -> 256x64) ----
    gemm_bias_t<256, 64><<<gridN300_256x64, 256>>>(node_feat, node_W, node_b, hn_p,
                                                   NN, DD, NF, nullptr, nullptr,
                                                   nullptr, nullptr);

    // ---- layers ----
    for (int l = 0; l < LL; l++) {
        const float* eW  = edge_W + (size_t)l * EFD * DD;
        const float* eb  = edge_b + (size_t)l * DD;
        const float* W1l = W1 + (size_t)l * DD * D2;
        const float* b1l = b1 + (size_t)l * D2;
        const float* g1l = g1 + (size_t)l * D2;
        const float* be1 = beta1 + (size_t)l * D2;
        const float* W2l = W2 + (size_t)l * D2 * DD;
        const float* b2l = b2 + (size_t)l * DD;
        const float* g2l = g2 + (size_t)l * DD;
        const float* be2 = beta2 + (size_t)l * DD;

        // fused edge encode + gather + relu + pull aggregate (+ residual)
        edge_agg_kernel<<<2368, 256>>>(hn_p, edge_feat, src, eidx_p, rowptr_p, eW, eb, A_p);

        // Y1 = A @ W1 + b1   [50000 x 600]  (N=600 -> 128x128), BN1 stats fused
        cudaMemsetAsync(sums1_p, 0, D2 * sizeof(double));
        cudaMemsetAsync(sqs1_p, 0, D2 * sizeof(double));
        gemm_bias_t<128, 128><<<gridN600_128x128, 256>>>(A_p, W1l, b1l, Y1_p,
                                                         NN, D2, DD, nullptr, nullptr,
                                                         sums1_p, sqs1_p);
        bn_coeff_kernel<<<(D2 + 255) / 256, 256>>>(sums1_p, sqs1_p, g1l, be1,
                                                   scale_p, shift_p, D2);

        // Y2 = relu(bn(Y1)) @ W2 + b2  (N=300 -> 256x64),
        // BN1+ReLU fused on A operand, BN2 stats fused in epilogue
        cudaMemsetAsync(sums2_p, 0, DD * sizeof(double));
        cudaMemsetAsync(sqs2_p, 0, DD * sizeof(double));
        gemm_bias_t<256, 64><<<gridN300_256x64, 256>>>(Y1_p, W2l, b2l, A_p,
                                                       NN, DD, D2, scale_p, shift_p,
                                                       sums2_p, sqs2_p);
        bn_coeff_kernel<<<(DD + 255) / 256, 256>>>(sums2_p, sqs2_p, g2l, be2,
                                                   scale_p, shift_p, DD);

        if (l != LL - 1) {
            // BN2 + ReLU -> hn (feeds next layer's gathers)
            bn_apply_kernel<<<(NN * DD + 255) / 256, 256>>>(A_p, hn_p, scale_p, shift_p,
                                                            DD, NN * DD, 1);
        } else {
            // final layer: BN2 (no relu) fused directly into avg-pool accumulation
            cudaMemsetAsync(hg_p, 0, GG * DD * sizeof(float));
            cudaMemsetAsync(cnt_p, 0, GG * sizeof(float));
            bn_apply_pool_kernel<<<(NN * DD + 255) / 256, 256>>>(A_p, scale_p, shift_p,
                                                                 graph_ids, hg_p);
            pool_cnt_kernel<<<(NN + 255) / 256, 256>>>(graph_ids, cnt_p);
        }
    }

    // ---- head ----
    head_kernel<<<GG, OUTD>>>(hg_p, cnt_p, pred_W, pred_b, out);
}